// round 9
// baseline (speedup 1.0000x reference)
#include <cuda_runtime.h>
#include <cstdint>

// Problem constants (fixed by the reference)
#define kN0 200000
#define kN1 50000
#define kN2 10000
#define kE1 1000000
#define kE2 250000
#define kCIN 128
#define kH   256

// ---------------------------------------------------------------------------
// Scratch (no cudaMalloc allowed -> __device__ globals)
// ---------------------------------------------------------------------------
__device__ float g_agg1[kN1 * kCIN];   // 6.4M floats
__device__ float g_cnt1[kN1];
__device__ float g_h[kN1 * kH];        // 12.8M floats (fully written by gemm1)
__device__ float g_agg2[kN2 * kH];     // 2.56M floats
__device__ float g_cnt2[kN2];

// ---------------------------------------------------------------------------
// Vector float4 global reduction (sm_90+)
// ---------------------------------------------------------------------------
__device__ __forceinline__ void red4(float* p, float4 v) {
    asm volatile("red.global.add.v4.f32 [%0], {%1,%2,%3,%4};"
                 :: "l"(p), "f"(v.x), "f"(v.y), "f"(v.z), "f"(v.w)
                 : "memory");
}

// ---------------------------------------------------------------------------
// Zero all scratch that is accumulated into (agg buffers + counts)
// ---------------------------------------------------------------------------
__global__ void zero_scratch() {
    const size_t n1 = (size_t)kN1 * kCIN;
    const size_t n2 = kN1;
    const size_t n3 = (size_t)kN2 * kH;
    const size_t n4 = kN2;
    const size_t total = n1 + n2 + n3 + n4;
    size_t stride = (size_t)gridDim.x * blockDim.x;
    for (size_t idx = (size_t)blockIdx.x * blockDim.x + threadIdx.x;
         idx < total; idx += stride) {
        if (idx < n1)                 g_agg1[idx] = 0.0f;
        else if (idx < n1 + n2)       g_cnt1[idx - n1] = 0.0f;
        else if (idx < n1 + n2 + n3)  g_agg2[idx - n1 - n2] = 0.0f;
        else                          g_cnt2[idx - n1 - n2 - n3] = 0.0f;
    }
}

// ---------------------------------------------------------------------------
// Layer 1 edge scatter: warp per edge, 128 channels = 1 float4/lane
// ---------------------------------------------------------------------------
__global__ __launch_bounds__(256)
void scatter1_kernel(const float* __restrict__ x,
                     const int* __restrict__ src,
                     const int* __restrict__ dst) {
    int e = (int)((blockIdx.x * (unsigned)blockDim.x + threadIdx.x) >> 5);
    int lane = threadIdx.x & 31;
    if (e >= kE1) return;
    int s = __ldg(src + e);
    int d = __ldg(dst + e);
    float4 v = ((const float4*)(x + (size_t)s * kCIN))[lane];
    red4(g_agg1 + (size_t)d * kCIN + lane * 4, v);
    if (lane == 0) atomicAdd(g_cnt1 + d, 1.0f);
}

// ---------------------------------------------------------------------------
// Layer 2 edge scatter: warp per edge, 256 channels = 2 float4/lane
// ---------------------------------------------------------------------------
__global__ __launch_bounds__(256)
void scatter2_kernel(const int* __restrict__ src,
                     const int* __restrict__ dst) {
    int e = (int)((blockIdx.x * (unsigned)blockDim.x + threadIdx.x) >> 5);
    int lane = threadIdx.x & 31;
    if (e >= kE2) return;
    int s = __ldg(src + e);
    int d = __ldg(dst + e);
    const float4* xp = (const float4*)(g_h + (size_t)s * kH);
    float4 v0 = xp[lane];
    float4 v1 = xp[lane + 32];
    float* op = g_agg2 + (size_t)d * kH;
    red4(op + lane * 4, v0);
    red4(op + 128 + lane * 4, v1);
    if (lane == 0) atomicAdd(g_cnt2 + d, 1.0f);
}

// ---------------------------------------------------------------------------
// Fused dual-input GEMM:
//   C[M,256] = act( (Aagg/cnt) @ Bl + Aden @ Br + bias )
// Both A halves have K = KA (row stride KA), B halves are [KA,256] row-major.
// Tile: 64x64, BK=16, 256 threads, 4x4 per thread, fp32 FFMA.
// ---------------------------------------------------------------------------
template<int KA, bool RELU>
__global__ __launch_bounds__(256)
void gemm_fused(const float* __restrict__ Aagg, const float* __restrict__ cnt,
                const float* __restrict__ Aden,
                const float* __restrict__ Bl,  const float* __restrict__ Br,
                const float* __restrict__ bias, float* __restrict__ C, int M) {
    __shared__ float As[16][65];   // transposed A tile (pad 65 for banking)
    __shared__ float Bs[16][64];

    const int tid = threadIdx.x;
    const int tx = tid & 15;
    const int ty = tid >> 4;
    const int i0 = blockIdx.y * 64;
    const int j0 = blockIdx.x * 64;

    // A-load mapping: row ar (0..63), k-offset ak (0,4,8,12)
    const int ar = tid >> 2;
    const int ak = (tid & 3) * 4;
    const int arow = i0 + ar;
    const bool avalid = arow < M;
    const float inv = avalid ? (1.0f / fmaxf(cnt[arow], 1.0f)) : 0.0f;

    // B-load mapping: k-row bk (0..15), col bj
    const int bk = tid >> 4;
    const int bj = (tid & 15) * 4;

    float acc[4][4] = {};

    #pragma unroll 1
    for (int kt = 0; kt < 2 * KA; kt += 16) {
        // ---- load A tile (choose agg-half or dense-half; 16 | KA so no split)
        float4 av = make_float4(0.f, 0.f, 0.f, 0.f);
        float s = 1.0f;
        if (avalid) {
            if (kt < KA) {
                av = *(const float4*)(Aagg + (size_t)arow * KA + kt + ak);
                s = inv;
            } else {
                av = *(const float4*)(Aden + (size_t)arow * KA + (kt - KA) + ak);
            }
        }
        As[ak + 0][ar] = av.x * s;
        As[ak + 1][ar] = av.y * s;
        As[ak + 2][ar] = av.z * s;
        As[ak + 3][ar] = av.w * s;

        // ---- load B tile
        {
            int k = kt + bk;
            const float* bp = (k < KA) ? (Bl + (size_t)k * 256)
                                       : (Br + (size_t)(k - KA) * 256);
            *(float4*)&Bs[bk][bj] = *(const float4*)(bp + j0 + bj);
        }
        __syncthreads();

        #pragma unroll
        for (int kk = 0; kk < 16; kk++) {
            float a0 = As[kk][ty * 4 + 0];
            float a1 = As[kk][ty * 4 + 1];
            float a2 = As[kk][ty * 4 + 2];
            float a3 = As[kk][ty * 4 + 3];
            float4 b = *(const float4*)&Bs[kk][tx * 4];
            acc[0][0] += a0 * b.x; acc[0][1] += a0 * b.y; acc[0][2] += a0 * b.z; acc[0][3] += a0 * b.w;
            acc[1][0] += a1 * b.x; acc[1][1] += a1 * b.y; acc[1][2] += a1 * b.z; acc[1][3] += a1 * b.w;
            acc[2][0] += a2 * b.x; acc[2][1] += a2 * b.y; acc[2][2] += a2 * b.z; acc[2][3] += a2 * b.w;
            acc[3][0] += a3 * b.x; acc[3][1] += a3 * b.y; acc[3][2] += a3 * b.z; acc[3][3] += a3 * b.w;
        }
        __syncthreads();
    }

    // ---- epilogue: + bias, optional relu, float4 store
    float4 bv = *(const float4*)(bias + j0 + tx * 4);
    #pragma unroll
    for (int ii = 0; ii < 4; ii++) {
        int i = i0 + ty * 4 + ii;
        if (i < M) {
            float4 o;
            o.x = acc[ii][0] + bv.x;
            o.y = acc[ii][1] + bv.y;
            o.z = acc[ii][2] + bv.z;
            o.w = acc[ii][3] + bv.w;
            if (RELU) {
                o.x = fmaxf(o.x, 0.f); o.y = fmaxf(o.y, 0.f);
                o.z = fmaxf(o.z, 0.f); o.w = fmaxf(o.w, 0.f);
            }
            *(float4*)(C + (size_t)i * 256 + j0 + tx * 4) = o;
        }
    }
}

// ---------------------------------------------------------------------------
// Launch
// ---------------------------------------------------------------------------
extern "C" void kernel_launch(void* const* d_in, const int* in_sizes, int n_in,
                              void* d_out, int out_size) {
    const float* x    = (const float*)d_in[0];
    const int*   src1 = (const int*)  d_in[1];
    const int*   dst1 = (const int*)  d_in[2];
    const int*   src2 = (const int*)  d_in[3];
    const int*   dst2 = (const int*)  d_in[4];
    const float* Wl1  = (const float*)d_in[5];
    const float* Wr1  = (const float*)d_in[6];
    const float* b1   = (const float*)d_in[7];
    const float* Wl2  = (const float*)d_in[8];
    const float* Wr2  = (const float*)d_in[9];
    const float* b2   = (const float*)d_in[10];
    float* out = (float*)d_out;

    // Resolve device-global scratch addresses at launch time via kernels
    // referencing the symbols directly (no cudaGetSymbolAddress needed).

    // 1) zero accumulation scratch
    zero_scratch<<<1184, 256>>>();   // 148 SMs * 8, grid-stride

    // 2) layer-1 scatter: 1M edges, 8 edges per 256-thread block
    scatter1_kernel<<<(kE1 + 7) / 8, 256>>>(x, src1, dst1);

    // 3) layer-1 fused GEMM + relu -> g_h  [50000 x 256]
    {
        dim3 grid(256 / 64, (kN1 + 63) / 64);
        float* gh;
        // direct symbol use inside kernel; pass pointers for the generic args
        // Aagg=g_agg1, cnt=g_cnt1, Aden=x, C=g_h -- we need device pointers.
        // Kernels can take __device__ array decay directly on the device side,
        // but from host we must pass symbol addresses; instead we declare the
        // kernel to use the globals via small wrappers below.
        (void)gh;
    }
    // Wrapper-free approach: get symbol addresses once per launch via the
    // (graph-capturable, non-allocating) runtime query.
    static float *p_agg1 = nullptr, *p_cnt1 = nullptr, *p_h = nullptr,
                 *p_agg2 = nullptr, *p_cnt2 = nullptr;
    if (!p_agg1) {
        cudaGetSymbolAddress((void**)&p_agg1, g_agg1);
        cudaGetSymbolAddress((void**)&p_cnt1, g_cnt1);
        cudaGetSymbolAddress((void**)&p_h,    g_h);
        cudaGetSymbolAddress((void**)&p_agg2, g_agg2);
        cudaGetSymbolAddress((void**)&p_cnt2, g_cnt2);
    }

    {
        dim3 grid(256 / 64, (kN1 + 63) / 64);
        gemm_fused<kCIN, true><<<grid, 256>>>(p_agg1, p_cnt1, x, Wl1, Wr1, b1,
                                              p_h, kN1);
    }

    // 4) layer-2 scatter: 250k edges
    scatter2_kernel<<<(kE2 + 7) / 8, 256>>>(src2, dst2);

    // 5) layer-2 fused GEMM -> d_out  [10000 x 256]
    {
        dim3 grid(256 / 64, (kN2 + 63) / 64);
        gemm_fused<kH, false><<<grid, 256>>>(p_agg2, p_cnt2, p_h, Wl2, Wr2, b2,
                                             out, kN2);
    }
}

// round 10
// speedup vs baseline: 1.0046x; 1.0046x over previous
#include <cuda_runtime.h>
#include <cstdint>

// Problem constants (fixed by the reference)
#define kN0 200000
#define kN1 50000
#define kN2 10000
#define kE1 1000000
#define kE2 250000
#define kCIN 128
#define kH   256

// ---------------------------------------------------------------------------
// Scratch (no cudaMalloc allowed -> __device__ globals)
// ---------------------------------------------------------------------------
__device__ float g_agg1[kN1 * kCIN];   // 6.4M floats
__device__ float g_cnt1[kN1];
__device__ float g_h[kN1 * kH];        // 12.8M floats (fully written by gemm1)
__device__ float g_agg2[kN2 * kH];     // 2.56M floats
__device__ float g_cnt2[kN2];

// ---------------------------------------------------------------------------
// Vector float4 global reduction (sm_90+)
// ---------------------------------------------------------------------------
__device__ __forceinline__ void red4(float* p, float4 v) {
    asm volatile("red.global.add.v4.f32 [%0], {%1,%2,%3,%4};"
                 :: "l"(p), "f"(v.x), "f"(v.y), "f"(v.z), "f"(v.w)
                 : "memory");
}

// ---------------------------------------------------------------------------
// Zero all scratch that is accumulated into (agg buffers + counts)
// ---------------------------------------------------------------------------
__global__ void zero_scratch() {
    const size_t n1 = (size_t)kN1 * kCIN;
    const size_t n2 = kN1;
    const size_t n3 = (size_t)kN2 * kH;
    const size_t n4 = kN2;
    const size_t total = n1 + n2 + n3 + n4;
    size_t stride = (size_t)gridDim.x * blockDim.x;
    for (size_t idx = (size_t)blockIdx.x * blockDim.x + threadIdx.x;
         idx < total; idx += stride) {
        if (idx < n1)                 g_agg1[idx] = 0.0f;
        else if (idx < n1 + n2)       g_cnt1[idx - n1] = 0.0f;
        else if (idx < n1 + n2 + n3)  g_agg2[idx - n1 - n2] = 0.0f;
        else                          g_cnt2[idx - n1 - n2 - n3] = 0.0f;
    }
}

// ---------------------------------------------------------------------------
// Layer 1 edge scatter: warp per edge, 128 channels = 1 float4/lane
// ---------------------------------------------------------------------------
__global__ __launch_bounds__(256)
void scatter1_kernel(const float* __restrict__ x,
                     const int* __restrict__ src,
                     const int* __restrict__ dst) {
    int e = (int)((blockIdx.x * (unsigned)blockDim.x + threadIdx.x) >> 5);
    int lane = threadIdx.x & 31;
    if (e >= kE1) return;
    int s = __ldg(src + e);
    int d = __ldg(dst + e);
    float4 v = ((const float4*)(x + (size_t)s * kCIN))[lane];
    red4(g_agg1 + (size_t)d * kCIN + lane * 4, v);
    if (lane == 0) atomicAdd(g_cnt1 + d, 1.0f);
}

// ---------------------------------------------------------------------------
// Layer 2 edge scatter: warp per edge, 256 channels = 2 float4/lane
// ---------------------------------------------------------------------------
__global__ __launch_bounds__(256)
void scatter2_kernel(const int* __restrict__ src,
                     const int* __restrict__ dst) {
    int e = (int)((blockIdx.x * (unsigned)blockDim.x + threadIdx.x) >> 5);
    int lane = threadIdx.x & 31;
    if (e >= kE2) return;
    int s = __ldg(src + e);
    int d = __ldg(dst + e);
    const float4* xp = (const float4*)(g_h + (size_t)s * kH);
    float4 v0 = xp[lane];
    float4 v1 = xp[lane + 32];
    float* op = g_agg2 + (size_t)d * kH;
    red4(op + lane * 4, v0);
    red4(op + 128 + lane * 4, v1);
    if (lane == 0) atomicAdd(g_cnt2 + d, 1.0f);
}

// ---------------------------------------------------------------------------
// Fused dual-input GEMM:
//   C[M,256] = act( (Aagg/cnt) @ Bl + Aden @ Br + bias )
// Both A halves have K = KA (row stride KA), B halves are [KA,256] row-major.
// Tile: 64x64, BK=16, 256 threads, 4x4 per thread, fp32 FFMA.
// ---------------------------------------------------------------------------
template<int KA, bool RELU>
__global__ __launch_bounds__(256)
void gemm_fused(const float* __restrict__ Aagg, const float* __restrict__ cnt,
                const float* __restrict__ Aden,
                const float* __restrict__ Bl,  const float* __restrict__ Br,
                const float* __restrict__ bias, float* __restrict__ C, int M) {
    __shared__ float As[16][65];   // transposed A tile (pad 65 for banking)
    __shared__ float Bs[16][64];

    const int tid = threadIdx.x;
    const int tx = tid & 15;
    const int ty = tid >> 4;
    const int i0 = blockIdx.y * 64;
    const int j0 = blockIdx.x * 64;

    // A-load mapping: row ar (0..63), k-offset ak (0,4,8,12)
    const int ar = tid >> 2;
    const int ak = (tid & 3) * 4;
    const int arow = i0 + ar;
    const bool avalid = arow < M;
    const float inv = avalid ? (1.0f / fmaxf(cnt[arow], 1.0f)) : 0.0f;

    // B-load mapping: k-row bk (0..15), col bj
    const int bk = tid >> 4;
    const int bj = (tid & 15) * 4;

    float acc[4][4] = {};

    #pragma unroll 1
    for (int kt = 0; kt < 2 * KA; kt += 16) {
        // ---- load A tile (choose agg-half or dense-half; 16 | KA so no split)
        float4 av = make_float4(0.f, 0.f, 0.f, 0.f);
        float s = 1.0f;
        if (avalid) {
            if (kt < KA) {
                av = *(const float4*)(Aagg + (size_t)arow * KA + kt + ak);
                s = inv;
            } else {
                av = *(const float4*)(Aden + (size_t)arow * KA + (kt - KA) + ak);
            }
        }
        As[ak + 0][ar] = av.x * s;
        As[ak + 1][ar] = av.y * s;
        As[ak + 2][ar] = av.z * s;
        As[ak + 3][ar] = av.w * s;

        // ---- load B tile
        {
            int k = kt + bk;
            const float* bp = (k < KA) ? (Bl + (size_t)k * 256)
                                       : (Br + (size_t)(k - KA) * 256);
            *(float4*)&Bs[bk][bj] = *(const float4*)(bp + j0 + bj);
        }
        __syncthreads();

        #pragma unroll
        for (int kk = 0; kk < 16; kk++) {
            float a0 = As[kk][ty * 4 + 0];
            float a1 = As[kk][ty * 4 + 1];
            float a2 = As[kk][ty * 4 + 2];
            float a3 = As[kk][ty * 4 + 3];
            float4 b = *(const float4*)&Bs[kk][tx * 4];
            acc[0][0] += a0 * b.x; acc[0][1] += a0 * b.y; acc[0][2] += a0 * b.z; acc[0][3] += a0 * b.w;
            acc[1][0] += a1 * b.x; acc[1][1] += a1 * b.y; acc[1][2] += a1 * b.z; acc[1][3] += a1 * b.w;
            acc[2][0] += a2 * b.x; acc[2][1] += a2 * b.y; acc[2][2] += a2 * b.z; acc[2][3] += a2 * b.w;
            acc[3][0] += a3 * b.x; acc[3][1] += a3 * b.y; acc[3][2] += a3 * b.z; acc[3][3] += a3 * b.w;
        }
        __syncthreads();
    }

    // ---- epilogue: + bias, optional relu, float4 store
    float4 bv = *(const float4*)(bias + j0 + tx * 4);
    #pragma unroll
    for (int ii = 0; ii < 4; ii++) {
        int i = i0 + ty * 4 + ii;
        if (i < M) {
            float4 o;
            o.x = acc[ii][0] + bv.x;
            o.y = acc[ii][1] + bv.y;
            o.z = acc[ii][2] + bv.z;
            o.w = acc[ii][3] + bv.w;
            if (RELU) {
                o.x = fmaxf(o.x, 0.f); o.y = fmaxf(o.y, 0.f);
                o.z = fmaxf(o.z, 0.f); o.w = fmaxf(o.w, 0.f);
            }
            *(float4*)(C + (size_t)i * 256 + j0 + tx * 4) = o;
        }
    }
}

// ---------------------------------------------------------------------------
// Launch
// ---------------------------------------------------------------------------
extern "C" void kernel_launch(void* const* d_in, const int* in_sizes, int n_in,
                              void* d_out, int out_size) {
    const float* x    = (const float*)d_in[0];
    const int*   src1 = (const int*)  d_in[1];
    const int*   dst1 = (const int*)  d_in[2];
    const int*   src2 = (const int*)  d_in[3];
    const int*   dst2 = (const int*)  d_in[4];
    const float* Wl1  = (const float*)d_in[5];
    const float* Wr1  = (const float*)d_in[6];
    const float* b1   = (const float*)d_in[7];
    const float* Wl2  = (const float*)d_in[8];
    const float* Wr2  = (const float*)d_in[9];
    const float* b2   = (const float*)d_in[10];
    float* out = (float*)d_out;

    // Resolve device-global scratch addresses at launch time via kernels
    // referencing the symbols directly (no cudaGetSymbolAddress needed).

    // 1) zero accumulation scratch
    zero_scratch<<<1184, 256>>>();   // 148 SMs * 8, grid-stride

    // 2) layer-1 scatter: 1M edges, 8 edges per 256-thread block
    scatter1_kernel<<<(kE1 + 7) / 8, 256>>>(x, src1, dst1);

    // 3) layer-1 fused GEMM + relu -> g_h  [50000 x 256]
    {
        dim3 grid(256 / 64, (kN1 + 63) / 64);
        float* gh;
        // direct symbol use inside kernel; pass pointers for the generic args
        // Aagg=g_agg1, cnt=g_cnt1, Aden=x, C=g_h -- we need device pointers.
        // Kernels can take __device__ array decay directly on the device side,
        // but from host we must pass symbol addresses; instead we declare the
        // kernel to use the globals via small wrappers below.
        (void)gh;
    }
    // Wrapper-free approach: get symbol addresses once per launch via the
    // (graph-capturable, non-allocating) runtime query.
    static float *p_agg1 = nullptr, *p_cnt1 = nullptr, *p_h = nullptr,
                 *p_agg2 = nullptr, *p_cnt2 = nullptr;
    if (!p_agg1) {
        cudaGetSymbolAddress((void**)&p_agg1, g_agg1);
        cudaGetSymbolAddress((void**)&p_cnt1, g_cnt1);
        cudaGetSymbolAddress((void**)&p_h,    g_h);
        cudaGetSymbolAddress((void**)&p_agg2, g_agg2);
        cudaGetSymbolAddress((void**)&p_cnt2, g_cnt2);
    }

    {
        dim3 grid(256 / 64, (kN1 + 63) / 64);
        gemm_fused<kCIN, true><<<grid, 256>>>(p_agg1, p_cnt1, x, Wl1, Wr1, b1,
                                              p_h, kN1);
    }

    // 4) layer-2 scatter: 250k edges
    scatter2_kernel<<<(kE2 + 7) / 8, 256>>>(src2, dst2);

    // 5) layer-2 fused GEMM -> d_out  [10000 x 256]
    {
        dim3 grid(256 / 64, (kN2 + 63) / 64);
        gemm_fused<kH, false><<<grid, 256>>>(p_agg2, p_cnt2, p_h, Wl2, Wr2, b2,
                                             out, kN2);
    }
}